// round 3
// baseline (speedup 1.0000x reference)
#include <cuda_runtime.h>
#include <cuda_bf16.h>
#include <cstdint>

// Problem constants
#define NN      64          // nodes
#define TT      512         // time steps
#define BB      64          // batch
#define PP      32          // window
#define KDIM    4096        // N*N
#define NCOLS   512         // T

// ---------------------------------------------------------------------------
// Scratch: softmaxed adjacency w[t][i][j], 512*4096 floats = 8 MB (static,
// allocation-free per harness rules).
// ---------------------------------------------------------------------------
__device__ float g_w[TT * KDIM];

// ---------------------------------------------------------------------------
// Kernel 1: F = g @ (weights^2)
//   A = g        [4096, 4096] row-major
//   B = weights  [4096, 512]  row-major (squared on load)
//   C = F        [4096, 512]  row-major
// 128x128x16 tile, 256 threads, 8x8 microtile using packed fma.rn.f32x2
// (exact fp32 semantics, 2x the scalar FFMA issue rate on sm_103a).
// ---------------------------------------------------------------------------
#define BM 128
#define BN 128
#define BK 16

__global__ __launch_bounds__(256, 1)
void sgemm_sq_kernel(const float* __restrict__ A,
                     const float* __restrict__ Bw,
                     float* __restrict__ C) {
    __shared__ float As[BK][BM + 4];   // +4 pad kills 4-way STS conflicts
    __shared__ float Bs[BK][BN];

    const int tid = threadIdx.x;
    const int bn  = blockIdx.x;        // 0..3   (columns of 128)
    const int bm  = blockIdx.y;        // 0..31  (rows of 128)
    const int tx  = tid & 15;          // 0..15
    const int ty  = tid >> 4;          // 0..15

    // Global-load assignments (float4)
    const int a_row = tid >> 2;        // 0..63  (+64 for h=1)
    const int a_col = (tid & 3) * 4;   // 0,4,8,12
    const int b_row = tid >> 5;        // 0..7   (+8 for h=1)
    const int b_col = (tid & 31) * 4;  // 0..124

    const float* Aptr = A  + (size_t)(bm * BM + a_row) * KDIM + a_col;
    const float* Bptr = Bw + (size_t)b_row * NCOLS + bn * BN + b_col;

    // Packed accumulators: acc[i][j] holds columns (tx*8 + 2j, tx*8 + 2j + 1)
    unsigned long long acc[8][4];
#pragma unroll
    for (int i = 0; i < 8; i++)
#pragma unroll
        for (int j = 0; j < 4; j++) acc[i][j] = 0ULL;

    float4 areg[2], breg[2];
    // Prefetch tile 0
#pragma unroll
    for (int h = 0; h < 2; h++) {
        areg[h] = *(const float4*)(Aptr + (size_t)h * 64 * KDIM);
        breg[h] = *(const float4*)(Bptr + (size_t)h * 8 * NCOLS);
    }

    const int KT = KDIM / BK;  // 256
    for (int kt = 0; kt < KT; kt++) {
        // Stage current tile into shared (square B here)
#pragma unroll
        for (int h = 0; h < 2; h++) {
            const int r = a_row + h * 64;
            float4 av = areg[h];
            As[a_col + 0][r] = av.x;
            As[a_col + 1][r] = av.y;
            As[a_col + 2][r] = av.z;
            As[a_col + 3][r] = av.w;
            float4 bv = breg[h];
            bv.x *= bv.x; bv.y *= bv.y; bv.z *= bv.z; bv.w *= bv.w;
            *(float4*)&Bs[b_row + h * 8][b_col] = bv;
        }
        __syncthreads();

        // Prefetch next tile into registers (overlaps with compute below)
        if (kt + 1 < KT) {
#pragma unroll
            for (int h = 0; h < 2; h++) {
                areg[h] = *(const float4*)(Aptr + (kt + 1) * BK +
                                           (size_t)h * 64 * KDIM);
                breg[h] = *(const float4*)(Bptr + (size_t)(kt + 1) * BK * NCOLS +
                                           (size_t)h * 8 * NCOLS);
            }
        }

        // Compute 16 k-steps
#pragma unroll
        for (int k = 0; k < BK; k++) {
            float a[8];
            *(float4*)&a[0] = *(const float4*)&As[k][ty * 8];
            *(float4*)&a[4] = *(const float4*)&As[k][ty * 8 + 4];
            unsigned long long bq[4];
            const unsigned long long* brow =
                (const unsigned long long*)&Bs[k][tx * 8];
            bq[0] = brow[0]; bq[1] = brow[1]; bq[2] = brow[2]; bq[3] = brow[3];
#pragma unroll
            for (int i = 0; i < 8; i++) {
                unsigned long long a2;
                asm("mov.b64 %0, {%1, %1};" : "=l"(a2) : "f"(a[i]));
#pragma unroll
                for (int j = 0; j < 4; j++) {
                    asm("fma.rn.f32x2 %0, %1, %2, %0;"
                        : "+l"(acc[i][j])
                        : "l"(a2), "l"(bq[j]));
                }
            }
        }
        __syncthreads();
    }

    // Epilogue
#pragma unroll
    for (int i = 0; i < 8; i++) {
        const int row = bm * BM + ty * 8 + i;
        float* crow = C + (size_t)row * NCOLS + bn * BN + tx * 8;
#pragma unroll
        for (int j = 0; j < 4; j++) {
            float lo, hi;
            asm("mov.b64 {%0, %1}, %2;" : "=f"(lo), "=f"(hi) : "l"(acc[i][j]));
            crow[2 * j]     = lo;
            crow[2 * j + 1] = hi;
        }
    }
}

// ---------------------------------------------------------------------------
// Kernel 2: w[t,i,j] = softmax_j F[i*64+j, t], stored as g_w[t*4096 + i*64 + j]
// Grid: (T/32, N) = (16, 64). Block: 256 threads.
// Tiled transpose in shared so both the F read (along t) and the w write
// (along j) are fully coalesced.
// ---------------------------------------------------------------------------
__global__ __launch_bounds__(256, 1)
void softmax_kernel(const float* __restrict__ F) {
    __shared__ float tile[64][33];   // [j][tt], padded
    const int tc  = blockIdx.x;      // t-chunk of 32
    const int i   = blockIdx.y;      // row group
    const int tid = threadIdx.x;

    const int tt = tid & 31;
    const int j0 = tid >> 5;         // 0..7
#pragma unroll
    for (int r = 0; r < 8; r++) {
        const int j = j0 + r * 8;
        tile[j][tt] = F[(size_t)(i * 64 + j) * NCOLS + tc * 32 + tt];
    }
    __syncthreads();

    if (tid < 32) {
        float m = -3.402823466e+38f;
#pragma unroll
        for (int j = 0; j < 64; j++) m = fmaxf(m, tile[j][tid]);
        float s = 0.f;
#pragma unroll
        for (int j = 0; j < 64; j++) {
            const float e = __expf(tile[j][tid] - m);
            tile[j][tid] = e;
            s += e;
        }
        const float inv = 1.f / s;
#pragma unroll
        for (int j = 0; j < 64; j++) tile[j][tid] *= inv;
    }
    __syncthreads();

#pragma unroll
    for (int idx = 0; idx < 8; idx++) {
        const int lin = tid + idx * 256;           // 0..2047
        const int ttw = lin >> 6;
        const int j   = lin & 63;
        g_w[(size_t)(tc * 32 + ttw) * KDIM + i * 64 + j] = tile[j][ttw];
    }
}

// ---------------------------------------------------------------------------
// Kernel 3: Z[b,n] = sum_{p,m} w[x_i[b,p], n, m] * x[b, m, p]
// Grid: B blocks, 256 threads: thread = (s = tid/64 handles 8 p's, n = tid%64)
// ---------------------------------------------------------------------------
__global__ __launch_bounds__(256, 1)
void gather_kernel(const float* __restrict__ x,
                   const int* __restrict__ xi,
                   float* __restrict__ Z) {
    __shared__ float xs[NN * PP];   // xs[m*32 + p] = x[b, m, p]
    __shared__ int   ti[PP];
    __shared__ float part[4][NN];

    const int b   = blockIdx.x;
    const int tid = threadIdx.x;

#pragma unroll
    for (int r = 0; r < 8; r++) {
        const int idx = tid + r * 256;
        xs[idx] = x[(size_t)b * (NN * PP) + idx];
    }
    if (tid < PP) ti[tid] = xi[b * PP + tid];
    __syncthreads();

    const int n = tid & 63;
    const int s = tid >> 6;   // 0..3
    float acc = 0.f;
#pragma unroll
    for (int pp = 0; pp < 8; pp++) {
        const int p = s * 8 + pp;
        const int t = ti[p];
        const float4* row =
            (const float4*)(g_w + (size_t)t * KDIM + n * 64);
#pragma unroll
        for (int q = 0; q < 16; q++) {
            const float4 v = row[q];
            const int m = q * 4;
            acc += v.x * xs[(m + 0) * 32 + p];
            acc += v.y * xs[(m + 1) * 32 + p];
            acc += v.z * xs[(m + 2) * 32 + p];
            acc += v.w * xs[(m + 3) * 32 + p];
        }
    }
    part[s][n] = acc;
    __syncthreads();
    if (tid < NN) {
        Z[b * NN + tid] =
            part[0][tid] + part[1][tid] + part[2][tid] + part[3][tid];
    }
}

// ---------------------------------------------------------------------------
// Launch: inputs per metadata order: x [B,N,P] f32, x_i [B,P] i32,
//         g [4096,4096] f32, weights [4096,512] f32.
// Output: Z [64,64] (4096 floats) followed by F [4096,512].
// ---------------------------------------------------------------------------
extern "C" void kernel_launch(void* const* d_in, const int* in_sizes, int n_in,
                              void* d_out, int out_size) {
    const float* x   = (const float*)d_in[0];
    const int*   xi  = (const int*)d_in[1];
    const float* g   = (const float*)d_in[2];
    const float* wts = (const float*)d_in[3];

    float* Z = (float*)d_out;
    float* F = (float*)d_out + NN * NN;   // F lives directly in the output

    dim3 ggrid(NCOLS / BN, KDIM / BM);    // (4, 32)
    sgemm_sq_kernel<<<ggrid, 256>>>(g, wts, F);

    dim3 sgrid(TT / 32, NN);              // (16, 64)
    softmax_kernel<<<sgrid, 256>>>(F);

    gather_kernel<<<BB, 256>>>(x, xi, Z);
}

// round 5
// speedup vs baseline: 2.1177x; 2.1177x over previous
#include <cuda_runtime.h>
#include <cuda_bf16.h>
#include <cstdint>

// Problem constants
#define NN      64          // nodes
#define TT      512         // time steps
#define BB      64          // batch
#define PP      32          // window
#define KDIM    4096        // N*N
#define NCOLS   512         // T

// ---------------------------------------------------------------------------
// Device scratch (static — allocation-free per harness rules)
// ---------------------------------------------------------------------------
__device__ float g_w[TT * KDIM];                       // softmaxed adjacency, 8 MB
__device__ __nv_bfloat16 g_hi[(size_t)KDIM * KDIM];    // 33.5 MB
__device__ __nv_bfloat16 g_lo[(size_t)KDIM * KDIM];    // 33.5 MB
__device__ __nv_bfloat16 w2t_hi[(size_t)NCOLS * KDIM]; // weights^2 transposed, 4 MB
__device__ __nv_bfloat16 w2t_lo[(size_t)NCOLS * KDIM]; // 4 MB

// ---------------------------------------------------------------------------
// PTX helpers (all baseline PTX, valid on plain sm_103 target)
// ---------------------------------------------------------------------------
__device__ __forceinline__ uint32_t smem_u32(const void* p) {
    uint32_t a;
    asm("{ .reg .u64 t; cvta.to.shared.u64 t, %1; cvt.u32.u64 %0, t; }"
        : "=r"(a) : "l"(p));
    return a;
}

__device__ __forceinline__ void cp16(uint32_t dst, const void* src) {
    asm volatile("cp.async.cg.shared.global [%0], [%1], 16;"
                 :: "r"(dst), "l"(src));
}

#define CP_COMMIT() asm volatile("cp.async.commit_group;" ::: "memory")
#define CP_WAIT1()  asm volatile("cp.async.wait_group 1;"  ::: "memory")

#define LDSM4(r, addr)                                                         \
    asm volatile("ldmatrix.sync.aligned.m8n8.x4.shared.b16 "                   \
                 "{%0,%1,%2,%3}, [%4];"                                        \
                 : "=r"((r)[0]), "=r"((r)[1]), "=r"((r)[2]), "=r"((r)[3])      \
                 : "r"(addr))

#define MMA16816(c, a, b0, b1)                                                 \
    asm volatile("mma.sync.aligned.m16n8k16.row.col.f32.bf16.bf16.f32 "        \
                 "{%0,%1,%2,%3},{%4,%5,%6,%7},{%8,%9},{%0,%1,%2,%3};"          \
                 : "+f"((c)[0]), "+f"((c)[1]), "+f"((c)[2]), "+f"((c)[3])      \
                 : "r"((a)[0]), "r"((a)[1]), "r"((a)[2]), "r"((a)[3]),         \
                   "r"(b0), "r"(b1))

// ---------------------------------------------------------------------------
// Kernel 0a: split g (fp32) into bf16 hi/lo
// ---------------------------------------------------------------------------
__global__ __launch_bounds__(256, 4)
void split_g_kernel(const float* __restrict__ g) {
    const int i = blockIdx.x * 256 + threadIdx.x;      // uint4 index
    const float4 v = ((const float4*)g)[i];
    const __nv_bfloat16 h0 = __float2bfloat16(v.x);
    const __nv_bfloat16 h1 = __float2bfloat16(v.y);
    const __nv_bfloat16 h2 = __float2bfloat16(v.z);
    const __nv_bfloat16 h3 = __float2bfloat16(v.w);
    const __nv_bfloat16 l0 = __float2bfloat16(v.x - __bfloat162float(h0));
    const __nv_bfloat16 l1 = __float2bfloat16(v.y - __bfloat162float(h1));
    const __nv_bfloat16 l2 = __float2bfloat16(v.z - __bfloat162float(h2));
    const __nv_bfloat16 l3 = __float2bfloat16(v.w - __bfloat162float(h3));
    uint2 hp, lp;
    hp.x = ((uint32_t)__bfloat16_as_ushort(h1) << 16) | __bfloat16_as_ushort(h0);
    hp.y = ((uint32_t)__bfloat16_as_ushort(h3) << 16) | __bfloat16_as_ushort(h2);
    lp.x = ((uint32_t)__bfloat16_as_ushort(l1) << 16) | __bfloat16_as_ushort(l0);
    lp.y = ((uint32_t)__bfloat16_as_ushort(l3) << 16) | __bfloat16_as_ushort(l2);
    ((uint2*)g_hi)[i] = hp;
    ((uint2*)g_lo)[i] = lp;
}

// ---------------------------------------------------------------------------
// Kernel 0b: weights -> weights^2, transposed to [T=512, K=4096], bf16 hi/lo
// ---------------------------------------------------------------------------
__global__ __launch_bounds__(256, 4)
void split_w_kernel(const float* __restrict__ w) {
    __shared__ float tile[32][33];
    const int kb = blockIdx.x;            // K blocks of 32
    const int nb = blockIdx.y;            // T blocks of 32
    const int tx = threadIdx.x & 31;
    const int ty = threadIdx.x >> 5;      // 0..7
#pragma unroll
    for (int r = 0; r < 4; r++) {
        const int k = kb * 32 + ty + r * 8;
        const float v = w[(size_t)k * NCOLS + nb * 32 + tx];
        tile[ty + r * 8][tx] = v * v;
    }
    __syncthreads();
#pragma unroll
    for (int r = 0; r < 4; r++) {
        const int n = nb * 32 + ty + r * 8;
        const int k = kb * 32 + tx;
        const float val = tile[tx][ty + r * 8];
        const __nv_bfloat16 h = __float2bfloat16(val);
        const __nv_bfloat16 l = __float2bfloat16(val - __bfloat162float(h));
        w2t_hi[(size_t)n * KDIM + k] = h;
        w2t_lo[(size_t)n * KDIM + k] = l;
    }
}

// ---------------------------------------------------------------------------
// Kernel 1: F = g @ weights^2 via mma.sync bf16 hi/lo split.
//   CTA tile 128x128, 256 threads = 8 warps (2 M x 4 N), warp tile 64x32.
//   K staged in chunks of 64 bf16 (128 B rows, SW128 swizzle, conflict-free
//   ldmatrix). 2-stage cp.async pipeline. 3 accumulating HMMA products:
//   hi*hi + hi*lo + lo*hi (drops ~2^-16 lo*lo term).
// ---------------------------------------------------------------------------
#define TILE_BYTES  16384                 // one [128 x 64] bf16 tile
#define STAGE_BYTES (4 * TILE_BYTES)      // Ahi | Alo | Bhi | Blo
#define SMEM_TOTAL  (2 * STAGE_BYTES)     // double buffered = 128 KB
#define KSTAGES     64

__global__ __launch_bounds__(256, 1)
void mma_gemm_kernel(float* __restrict__ F) {
    extern __shared__ char smem[];
    const uint32_t sb = smem_u32(smem);
    const int tid  = threadIdx.x;
    const int lane = tid & 31;
    const int wid  = tid >> 5;
    const int bn = blockIdx.x;            // 0..3   (128-col tiles of T)
    const int bm = blockIdx.y;            // 0..31  (128-row tiles of N*N)
    const int wm = wid >> 2;              // 0..1 -> row offset wm*64
    const int wn = wid & 3;               // 0..3 -> col offset wn*32

    const __nv_bfloat16* Ah = g_hi   + (size_t)(bm * 128) * KDIM;
    const __nv_bfloat16* Al = g_lo   + (size_t)(bm * 128) * KDIM;
    const __nv_bfloat16* Bh = w2t_hi + (size_t)(bn * 128) * KDIM;
    const __nv_bfloat16* Bl = w2t_lo + (size_t)(bn * 128) * KDIM;

    // Per-thread load slots: id = tid + v*256 -> row = id/8, c16 = id%8
    const int ld_row = tid >> 3;          // base row (stride 32 over v)
    const int ld_c16 = tid & 7;

    float c[4][4][4];
#pragma unroll
    for (int mt = 0; mt < 4; mt++)
#pragma unroll
        for (int nt = 0; nt < 4; nt++)
#pragma unroll
            for (int q = 0; q < 4; q++) c[mt][nt][q] = 0.f;

    // ---- stage loader (issues 16 cp.async of 16B, then commit) ----
    auto issue_stage = [&](int s, int buf) {
        const uint32_t base = sb + buf * STAGE_BYTES;
        const size_t kof = (size_t)s * 64;
#pragma unroll
        for (int v = 0; v < 4; v++) {
            const int row = ld_row + v * 32;
            uint32_t off = (uint32_t)(row * 128 + ld_c16 * 16);
            off ^= (off >> 3) & 0x70;                 // SW128 swizzle
            const size_t gi = (size_t)row * KDIM + kof + ld_c16 * 8;
            cp16(base + off,                  Ah + gi);
            cp16(base + TILE_BYTES + off,     Al + gi);
            cp16(base + 2 * TILE_BYTES + off, Bh + gi);
            cp16(base + 3 * TILE_BYTES + off, Bl + gi);
        }
    };

    // Prologue: stages 0 and 1 in flight
    issue_stage(0, 0); CP_COMMIT();
    issue_stage(1, 1); CP_COMMIT();

    const int rA = lane & 15;             // ldmatrix row-within-16
    const int kHalf = (lane >> 4) << 4;   // +16B for lanes 16..31

    for (int s = 0; s < KSTAGES; s++) {
        const int buf = s & 1;
        CP_WAIT1();
        __syncthreads();

        const uint32_t ab = sb + buf * STAGE_BYTES;
        const uint32_t al = ab + TILE_BYTES;
        const uint32_t bh = ab + 2 * TILE_BYTES;
        const uint32_t bl = ab + 3 * TILE_BYTES;

#pragma unroll
        for (int kk = 0; kk < 4; kk++) {          // 4 x K=16 within the chunk
            const int kb = kk * 32 + kHalf;       // byte offset in 128B row

            uint32_t ahr[4][4], alr[4][4];
#pragma unroll
            for (int mt = 0; mt < 4; mt++) {
                const int row = wm * 64 + mt * 16 + rA;
                uint32_t off = (uint32_t)(row * 128 + kb);
                off ^= (off >> 3) & 0x70;
                LDSM4(ahr[mt], ab + off);
                LDSM4(alr[mt], al + off);
            }
            uint32_t bhr[2][4], blr[2][4];
#pragma unroll
            for (int g = 0; g < 2; g++) {
                const int row = wn * 32 + g * 16 + rA;
                uint32_t off = (uint32_t)(row * 128 + kb);
                off ^= (off >> 3) & 0x70;
                LDSM4(bhr[g], bh + off);
                LDSM4(blr[g], bl + off);
            }

#pragma unroll
            for (int mt = 0; mt < 4; mt++)
#pragma unroll
                for (int nt = 0; nt < 4; nt++) {
                    const int g = nt >> 1, h = nt & 1;
                    MMA16816(c[mt][nt], ahr[mt], bhr[g][h], bhr[g][h + 2]);
                    MMA16816(c[mt][nt], ahr[mt], blr[g][h], blr[g][h + 2]);
                    MMA16816(c[mt][nt], alr[mt], bhr[g][h], bhr[g][h + 2]);
                }
        }

        __syncthreads();                  // everyone done reading buf
        if (s + 2 < KSTAGES) issue_stage(s + 2, buf);
        CP_COMMIT();                      // commit (possibly empty) group
    }

    // Epilogue: fragment -> F (row-major [4096, 512])
    const int r_lo = lane >> 2;           // 0..7
    const int c_lo = (lane & 3) * 2;
#pragma unroll
    for (int mt = 0; mt < 4; mt++) {
        const int row0 = bm * 128 + wm * 64 + mt * 16 + r_lo;
#pragma unroll
        for (int nt = 0; nt < 4; nt++) {
            const int col = bn * 128 + wn * 32 + nt * 8 + c_lo;
            float2 v0 = make_float2(c[mt][nt][0], c[mt][nt][1]);
            float2 v1 = make_float2(c[mt][nt][2], c[mt][nt][3]);
            *(float2*)(F + (size_t)row0 * NCOLS + col)       = v0;
            *(float2*)(F + (size_t)(row0 + 8) * NCOLS + col) = v1;
        }
    }
}

// ---------------------------------------------------------------------------
// Kernel 2: w[t,i,j] = softmax_j F[i*64+j, t]  -> g_w[t*4096 + i*64 + j]
// ---------------------------------------------------------------------------
__global__ __launch_bounds__(256, 1)
void softmax_kernel(const float* __restrict__ F) {
    __shared__ float tile[64][33];
    const int tc  = blockIdx.x;      // t-chunk of 32
    const int i   = blockIdx.y;
    const int tid = threadIdx.x;

    const int tt = tid & 31;
    const int j0 = tid >> 5;
#pragma unroll
    for (int r = 0; r < 8; r++) {
        const int j = j0 + r * 8;
        tile[j][tt] = F[(size_t)(i * 64 + j) * NCOLS + tc * 32 + tt];
    }
    __syncthreads();

    if (tid < 32) {
        float m = -3.402823466e+38f;
#pragma unroll
        for (int j = 0; j < 64; j++) m = fmaxf(m, tile[j][tid]);
        float s = 0.f;
#pragma unroll
        for (int j = 0; j < 64; j++) {
            const float e = __expf(tile[j][tid] - m);
            tile[j][tid] = e;
            s += e;
        }
        const float inv = 1.f / s;
#pragma unroll
        for (int j = 0; j < 64; j++) tile[j][tid] *= inv;
    }
    __syncthreads();

#pragma unroll
    for (int idx = 0; idx < 8; idx++) {
        const int lin = tid + idx * 256;
        const int ttw = lin >> 6;
        const int j   = lin & 63;
        g_w[(size_t)(tc * 32 + ttw) * KDIM + i * 64 + j] = tile[j][ttw];
    }
}

// ---------------------------------------------------------------------------
// Kernel 3: Z[b,n] = sum_{p,m} w[x_i[b,p], n, m] * x[b, m, p]
// ---------------------------------------------------------------------------
__global__ __launch_bounds__(256, 1)
void gather_kernel(const float* __restrict__ x,
                   const int* __restrict__ xi,
                   float* __restrict__ Z) {
    __shared__ float xs[NN * PP];
    __shared__ int   ti[PP];
    __shared__ float part[4][NN];

    const int b   = blockIdx.x;
    const int tid = threadIdx.x;

#pragma unroll
    for (int r = 0; r < 8; r++) {
        const int idx = tid + r * 256;
        xs[idx] = x[(size_t)b * (NN * PP) + idx];
    }
    if (tid < PP) ti[tid] = xi[b * PP + tid];
    __syncthreads();

    const int n = tid & 63;
    const int s = tid >> 6;
    float acc = 0.f;
#pragma unroll
    for (int pp = 0; pp < 8; pp++) {
        const int p = s * 8 + pp;
        const int t = ti[p];
        const float4* row = (const float4*)(g_w + (size_t)t * KDIM + n * 64);
#pragma unroll
        for (int q = 0; q < 16; q++) {
            const float4 v = row[q];
            const int m = q * 4;
            acc += v.x * xs[(m + 0) * 32 + p];
            acc += v.y * xs[(m + 1) * 32 + p];
            acc += v.z * xs[(m + 2) * 32 + p];
            acc += v.w * xs[(m + 3) * 32 + p];
        }
    }
    part[s][n] = acc;
    __syncthreads();
    if (tid < NN) {
        Z[b * NN + tid] =
            part[0][tid] + part[1][tid] + part[2][tid] + part[3][tid];
    }
}

// ---------------------------------------------------------------------------
// Launch. Inputs: x [B,N,P] f32, x_i [B,P] i32, g [4096,4096] f32,
//                 weights [4096,512] f32.  Output: Z (4096 f32) then F.
// ---------------------------------------------------------------------------
extern "C" void kernel_launch(void* const* d_in, const int* in_sizes, int n_in,
                              void* d_out, int out_size) {
    const float* x   = (const float*)d_in[0];
    const int*   xi  = (const int*)d_in[1];
    const float* g   = (const float*)d_in[2];
    const float* wts = (const float*)d_in[3];

    float* Z = (float*)d_out;
    float* F = (float*)d_out + NN * NN;

    cudaFuncSetAttribute(mma_gemm_kernel,
                         cudaFuncAttributeMaxDynamicSharedMemorySize, SMEM_TOTAL);

    split_g_kernel<<<(KDIM * (size_t)KDIM) / 4 / 256, 256>>>(g);
    split_w_kernel<<<dim3(KDIM / 32, NCOLS / 32), 256>>>(wts);

    mma_gemm_kernel<<<dim3(NCOLS / 128, KDIM / 128), 256, SMEM_TOTAL>>>(F);

    softmax_kernel<<<dim3(TT / 32, NN), 256>>>(F);
    gather_kernel<<<BB, 256>>>(x, xi, Z);
}